// round 1
// baseline (speedup 1.0000x reference)
#include <cuda_runtime.h>
#include <math.h>

#define S   2048
#define D   64
#define BH  32

// Deterministic column-sum scratch (each K1 block owns its 128 columns exclusively).
__device__ float g_NC[BH * S];

// ---------- packed fp32x2 helpers (FFMA2 path: 2x fp32 FMA throughput) ----------
__device__ __forceinline__ unsigned long long pk2(float x, float y) {
    unsigned long long r;
    asm("mov.b64 %0, {%1, %2};" : "=l"(r) : "f"(x), "f"(y));
    return r;
}
__device__ __forceinline__ void upk2(unsigned long long v, float &x, float &y) {
    asm("mov.b64 {%0, %1}, %2;" : "=f"(x), "=f"(y) : "l"(v));
}
__device__ __forceinline__ void ffma2(unsigned long long &d, unsigned long long a,
                                      unsigned long long b) {
    asm("fma.rn.f32x2 %0, %1, %2, %0;" : "+l"(d) : "l"(a), "l"(b));
}

// ============================================================================
// Kernel 1: raw scores s = exp(-acos(clip(q.k))^2) -> attn buffer,
//           column sums N_C -> g_NC.
// grid (16 ktiles, 32 bh), 256 threads. Tile N=128 k-cols, loop q in chunks of 128.
// smem: Ks transposed [64][132] (k-major), Qs natural [128][68].
// ============================================================================
#define K1_KSTRIDE 132
#define K1_QSTRIDE 68
#define K1_SMEM ((64 * K1_KSTRIDE + 128 * K1_QSTRIDE) * 4)

__global__ __launch_bounds__(256, 2)
void k_scores(const float* __restrict__ Qg_, const float* __restrict__ Kg_,
              float* __restrict__ attn) {
    extern __shared__ float sm[];
    float* Ks = sm;                       // 64 * 132
    float* Qs = sm + 64 * K1_KSTRIDE;     // 128 * 68

    const int kb  = blockIdx.x * 128;
    const int bh  = blockIdx.y;
    const int tid = threadIdx.x;
    const int tm  = tid >> 4;   // 0..15 -> q rows tm*8..+7
    const int tn  = tid & 15;   // 0..15 -> k cols tn*8..+7

    const float* Qg = Qg_ + (size_t)bh * S * D;
    const float* Kg = Kg_ + (size_t)bh * S * D;
    float*       Ag = attn + (size_t)bh * S * S;

    // Load K tile once per block, transposed to k-major [d][n] (stride 132).
    for (int t = tid; t < 128 * 16; t += 256) {
        int n = t >> 4, c4 = t & 15;
        float4 v = *(const float4*)(Kg + (size_t)(kb + n) * D + c4 * 4);
        Ks[(c4 * 4 + 0) * K1_KSTRIDE + n] = v.x;
        Ks[(c4 * 4 + 1) * K1_KSTRIDE + n] = v.y;
        Ks[(c4 * 4 + 2) * K1_KSTRIDE + n] = v.z;
        Ks[(c4 * 4 + 3) * K1_KSTRIDE + n] = v.w;
    }

    float cs[8];
#pragma unroll
    for (int j = 0; j < 8; j++) cs[j] = 0.f;

    for (int qb = 0; qb < S; qb += 128) {
        __syncthreads();
        // Load Q chunk natural [m][d] (stride 68) — conflict-free float4 stores.
        for (int t = tid; t < 128 * 16; t += 256) {
            int m = t >> 4, c4 = t & 15;
            *(float4*)(Qs + m * K1_QSTRIDE + c4 * 4) =
                *(const float4*)(Qg + (size_t)(qb + m) * D + c4 * 4);
        }
        __syncthreads();

        unsigned long long acc[8][4];
#pragma unroll
        for (int i = 0; i < 8; i++)
#pragma unroll
            for (int j = 0; j < 4; j++) acc[i][j] = 0ull;

#pragma unroll 8
        for (int kk = 0; kk < 64; kk++) {
            // b: 8 consecutive k-cols as 4 natural fp32x2 pairs
            ulonglong2 b0 = *(const ulonglong2*)(Ks + kk * K1_KSTRIDE + tn * 8);
            ulonglong2 b1 = *(const ulonglong2*)(Ks + kk * K1_KSTRIDE + tn * 8 + 4);
            unsigned long long av[8];
#pragma unroll
            for (int i = 0; i < 8; i++) {
                float a = Qs[(tm * 8 + i) * K1_QSTRIDE + kk];  // broadcast LDS
                av[i] = pk2(a, a);
            }
#pragma unroll
            for (int i = 0; i < 8; i++) {
                ffma2(acc[i][0], av[i], b0.x);
                ffma2(acc[i][1], av[i], b0.y);
                ffma2(acc[i][2], av[i], b1.x);
                ffma2(acc[i][3], av[i], b1.y);
            }
        }

        // Transform + store raw scores, accumulate column sums.
#pragma unroll
        for (int i = 0; i < 8; i++) {
            float s[8];
            upk2(acc[i][0], s[0], s[1]);
            upk2(acc[i][1], s[2], s[3]);
            upk2(acc[i][2], s[4], s[5]);
            upk2(acc[i][3], s[6], s[7]);
#pragma unroll
            for (int j = 0; j < 8; j++) {
                float dd = fminf(1.f, fmaxf(-1.f, s[j]));
                float g  = acosf(dd);
                s[j] = __expf(-g * g);
                cs[j] += s[j];
            }
            size_t base = (size_t)(qb + tm * 8 + i) * S + kb + tn * 8;
            *(float4*)(Ag + base)     = make_float4(s[0], s[1], s[2], s[3]);
            *(float4*)(Ag + base + 4) = make_float4(s[4], s[5], s[6], s[7]);
        }
    }

    // Deterministic column-sum reduction (reuse Qs as scratch: 16x128 floats).
    __syncthreads();
    float* red = Qs;
#pragma unroll
    for (int j = 0; j < 8; j++) red[tm * 128 + tn * 8 + j] = cs[j];
    __syncthreads();
    if (tid < 128) {
        float t = 0.f;
#pragma unroll
        for (int i = 0; i < 16; i++) t += red[i * 128 + tid];
        g_NC[bh * S + kb + tid] = t;
    }
}

// ============================================================================
// Kernel 2 (fused): per q-strip of 128 rows:
//   phase A: rc[k] = rsqrt(N_C[k])  (smem, 2048)
//   phase B: rowsum r[q] = sum_k s[q,k]*rc[k]  -> rinv[q] = 1/r
//   phase C: stream k-chunks of 64: w = s*rc*rinv, write w back in-place,
//            accumulate O += w @ V  (FFMA2 register-blocked GEMM)
// grid (16 qtiles, 32 bh), 256 threads.
// smem: rc[2048] | rinv[128] | Ws[64][132] | Vs[64][68]
// ============================================================================
#define K3_WSTRIDE 132
#define K3_VSTRIDE 68
#define K3_SMEM ((2048 + 128 + 64 * K3_WSTRIDE + 64 * K3_VSTRIDE) * 4)

__global__ __launch_bounds__(256, 2)
void k_av(const float* __restrict__ Vg_, float* __restrict__ attn,
          float* __restrict__ Og_) {
    extern __shared__ float sm[];
    float* rc   = sm;                      // 2048
    float* rinv = sm + 2048;               // 128
    float* Ws   = sm + 2048 + 128;         // 64*132
    float* Vs   = Ws + 64 * K3_WSTRIDE;    // 64*68

    const int bh  = blockIdx.y;
    const int qb  = blockIdx.x * 128;
    const int tid = threadIdx.x;

    float*       Ag = attn + (size_t)bh * S * S;
    const float* Vg = Vg_ + (size_t)bh * S * D;
    float*       Og = Og_ + (size_t)bh * S * D;

    // phase A: rc
    for (int t = tid; t < S; t += 256) rc[t] = rsqrtf(g_NC[bh * S + t]);
    __syncthreads();

    // phase B: rowsums (8 warps x 16 rows)
    {
        const int w = tid >> 5, l = tid & 31;
        const float4* rc4 = (const float4*)rc;
        for (int rr = 0; rr < 16; rr++) {
            int q = qb + w * 16 + rr;
            const float4* row = (const float4*)(Ag + (size_t)q * S);
            float acc = 0.f;
#pragma unroll 4
            for (int it = 0; it < 16; it++) {
                float4 a = row[it * 32 + l];
                float4 c = rc4[it * 32 + l];
                acc += a.x * c.x + a.y * c.y + a.z * c.z + a.w * c.w;
            }
#pragma unroll
            for (int off = 16; off; off >>= 1)
                acc += __shfl_xor_sync(0xffffffffu, acc, off);
            if (l == 0) rinv[w * 16 + rr] = 1.f / acc;
        }
    }
    __syncthreads();

    // phase C: weights + AV GEMM
    const int tq = tid >> 4;  // 0..15 -> q rows tq*8..+7 (paired)
    const int td = tid & 15;  // 0..15 -> d cols td*4..+3
    unsigned long long acc[4][4];
#pragma unroll
    for (int p = 0; p < 4; p++)
#pragma unroll
        for (int j = 0; j < 4; j++) acc[p][j] = 0ull;

    for (int cb = 0; cb < S; cb += 64) {
        __syncthreads();
        // load scores chunk, rescale to final weights, write back, stage transposed
        for (int t = tid; t < 128 * 16; t += 256) {
            int m = t >> 4, c4 = t & 15;
            float* gp = Ag + (size_t)(qb + m) * S + cb + c4 * 4;
            float4 sv = *(const float4*)gp;
            float  ri = rinv[m];
            float4 wv;
            wv.x = sv.x * rc[cb + c4 * 4 + 0] * ri;
            wv.y = sv.y * rc[cb + c4 * 4 + 1] * ri;
            wv.z = sv.z * rc[cb + c4 * 4 + 2] * ri;
            wv.w = sv.w * rc[cb + c4 * 4 + 3] * ri;
            *(float4*)gp = wv;  // final attn_weights
            int kx = c4 * 4;
            Ws[(kx + 0) * K3_WSTRIDE + m] = wv.x;
            Ws[(kx + 1) * K3_WSTRIDE + m] = wv.y;
            Ws[(kx + 2) * K3_WSTRIDE + m] = wv.z;
            Ws[(kx + 3) * K3_WSTRIDE + m] = wv.w;
        }
        // load V chunk natural [k][d]
        for (int t = tid; t < 64 * 16; t += 256) {
            int k = t >> 4, c4 = t & 15;
            *(float4*)(Vs + k * K3_VSTRIDE + c4 * 4) =
                *(const float4*)(Vg + (size_t)(cb + k) * D + c4 * 4);
        }
        __syncthreads();

#pragma unroll 8
        for (int kk = 0; kk < 64; kk++) {
            // a: 8 q-rows as 4 natural fp32x2 pairs (k-major Ws)
            ulonglong2 a01 = *(const ulonglong2*)(Ws + kk * K3_WSTRIDE + tq * 8);
            ulonglong2 a23 = *(const ulonglong2*)(Ws + kk * K3_WSTRIDE + tq * 8 + 4);
            float4 bv = *(const float4*)(Vs + kk * K3_VSTRIDE + td * 4);
            unsigned long long bd[4] = {pk2(bv.x, bv.x), pk2(bv.y, bv.y),
                                        pk2(bv.z, bv.z), pk2(bv.w, bv.w)};
            unsigned long long aa[4] = {a01.x, a01.y, a23.x, a23.y};
#pragma unroll
            for (int p = 0; p < 4; p++) {
                ffma2(acc[p][0], aa[p], bd[0]);
                ffma2(acc[p][1], aa[p], bd[1]);
                ffma2(acc[p][2], aa[p], bd[2]);
                ffma2(acc[p][3], aa[p], bd[3]);
            }
        }
    }

    // store O
#pragma unroll
    for (int p = 0; p < 4; p++) {
        float x0, y0, x1, y1, x2, y2, x3, y3;
        upk2(acc[p][0], x0, y0);
        upk2(acc[p][1], x1, y1);
        upk2(acc[p][2], x2, y2);
        upk2(acc[p][3], x3, y3);
        int q0 = qb + tq * 8 + 2 * p;
        *(float4*)(Og + (size_t)q0 * D + td * 4)       = make_float4(x0, x1, x2, x3);
        *(float4*)(Og + (size_t)(q0 + 1) * D + td * 4) = make_float4(y0, y1, y2, y3);
    }
}

// ============================================================================
extern "C" void kernel_launch(void* const* d_in, const int* in_sizes, int n_in,
                              void* d_out, int out_size) {
    const float* q = (const float*)d_in[0];
    const float* k = (const float*)d_in[1];
    const float* v = (const float*)d_in[2];
    // d_in[3] = attn_mask (all False) — no-op in reference, ignored.

    float* out  = (float*)d_out;
    float* O    = out;                       // [B,H,S,D] = 4,194,304 floats
    float* attn = out + (size_t)BH * S * D;  // [B,H,S,S]

    cudaFuncSetAttribute(k_scores, cudaFuncAttributeMaxDynamicSharedMemorySize, K1_SMEM);
    cudaFuncSetAttribute(k_av,     cudaFuncAttributeMaxDynamicSharedMemorySize, K3_SMEM);

    dim3 g1(S / 128, BH);
    k_scores<<<g1, 256, K1_SMEM>>>(q, k, attn);
    dim3 g2(S / 128, BH);
    k_av<<<g2, 256, K3_SMEM>>>(v, attn, O);
}

// round 2
// speedup vs baseline: 1.0610x; 1.0610x over previous
#include <cuda_runtime.h>
#include <math.h>

#define S   2048
#define D   64
#define BH  32

// Deterministic scratch. Each k1 block owns its 128 columns exclusively.
__device__ float g_NC[BH * S];   // column sums
__device__ float g_RC[BH * S];   // rsqrt(N_C)
__device__ float g_RS[BH * S];   // 1 / (sum_k s[q,k]*rc[k])

// ---------- packed fp32x2 helpers (FFMA2 path: 2x fp32 FMA throughput) ----------
__device__ __forceinline__ unsigned long long pk2(float x, float y) {
    unsigned long long r;
    asm("mov.b64 %0, {%1, %2};" : "=l"(r) : "f"(x), "f"(y));
    return r;
}
__device__ __forceinline__ void upk2(unsigned long long v, float &x, float &y) {
    asm("mov.b64 {%0, %1}, %2;" : "=f"(x), "=f"(y) : "l"(v));
}
__device__ __forceinline__ void ffma2(unsigned long long &d, unsigned long long a,
                                      unsigned long long b) {
    asm("fma.rn.f32x2 %0, %1, %2, %0;" : "+l"(d) : "l"(a), "l"(b));
}

// acos(1-t)^2 = 2t * P(t)^2, P = Taylor of acos(1-t)/sqrt(2t) (radius t=2).
// Coefficients a_n = (2n)! / (4^n (n!)^2 (2n+1) 2^n), exact.
__device__ __forceinline__ float score_xform(float dot) {
    float t = 1.0f - dot;
    t = fminf(fmaxf(t, 0.0f), 2.0f);
    float p = 1.9066e-5f;                 // a9
    p = fmaf(p, t, 4.5125e-5f);           // a8
    p = fmaf(p, t, 1.09101e-4f);          // a7
    p = fmaf(p, t, 2.71137e-4f);          // a6
    p = fmaf(p, t, 6.99129e-4f);          // a5
    p = fmaf(p, t, 1.89887e-3f);          // a4
    p = fmaf(p, t, 5.58036e-3f);          // a3
    p = fmaf(p, t, 1.875e-2f);            // a2
    p = fmaf(p, t, 8.3333333e-2f);        // a1
    p = fmaf(p, t, 1.0f);                 // a0
    float phi = (t + t) * p * p;          // acos^2
    return __expf(-phi);
}

// ============================================================================
// Kernel 1: raw scores s = exp(-acos(clip(q.k))^2) -> attn buffer,
//           column sums N_C -> g_NC.
// ============================================================================
#define K1_KSTRIDE 132
#define K1_QSTRIDE 68
#define K1_SMEM ((64 * K1_KSTRIDE + 128 * K1_QSTRIDE) * 4)

__global__ __launch_bounds__(256, 2)
void k_scores(const float* __restrict__ Qg_, const float* __restrict__ Kg_,
              float* __restrict__ attn) {
    extern __shared__ float sm[];
    float* Ks = sm;                       // 64 * 132
    float* Qs = sm + 64 * K1_KSTRIDE;     // 128 * 68

    const int kb  = blockIdx.x * 128;
    const int bh  = blockIdx.y;
    const int tid = threadIdx.x;
    const int tm  = tid >> 4;   // q rows tm*8..+7
    const int tn  = tid & 15;   // k cols tn*8..+7

    const float* Qg = Qg_ + (size_t)bh * S * D;
    const float* Kg = Kg_ + (size_t)bh * S * D;
    float*       Ag = attn + (size_t)bh * S * S;

    for (int t = tid; t < 128 * 16; t += 256) {
        int n = t >> 4, c4 = t & 15;
        float4 v = *(const float4*)(Kg + (size_t)(kb + n) * D + c4 * 4);
        Ks[(c4 * 4 + 0) * K1_KSTRIDE + n] = v.x;
        Ks[(c4 * 4 + 1) * K1_KSTRIDE + n] = v.y;
        Ks[(c4 * 4 + 2) * K1_KSTRIDE + n] = v.z;
        Ks[(c4 * 4 + 3) * K1_KSTRIDE + n] = v.w;
    }

    float cs[8];
#pragma unroll
    for (int j = 0; j < 8; j++) cs[j] = 0.f;

    for (int qb = 0; qb < S; qb += 128) {
        __syncthreads();
        for (int t = tid; t < 128 * 16; t += 256) {
            int m = t >> 4, c4 = t & 15;
            *(float4*)(Qs + m * K1_QSTRIDE + c4 * 4) =
                *(const float4*)(Qg + (size_t)(qb + m) * D + c4 * 4);
        }
        __syncthreads();

        unsigned long long acc[8][4];
#pragma unroll
        for (int i = 0; i < 8; i++)
#pragma unroll
            for (int j = 0; j < 4; j++) acc[i][j] = 0ull;

#pragma unroll 8
        for (int kk = 0; kk < 64; kk++) {
            ulonglong2 b0 = *(const ulonglong2*)(Ks + kk * K1_KSTRIDE + tn * 8);
            ulonglong2 b1 = *(const ulonglong2*)(Ks + kk * K1_KSTRIDE + tn * 8 + 4);
            unsigned long long av[8];
#pragma unroll
            for (int i = 0; i < 8; i++) {
                float a = Qs[(tm * 8 + i) * K1_QSTRIDE + kk];
                av[i] = pk2(a, a);
            }
#pragma unroll
            for (int i = 0; i < 8; i++) {
                ffma2(acc[i][0], av[i], b0.x);
                ffma2(acc[i][1], av[i], b0.y);
                ffma2(acc[i][2], av[i], b1.x);
                ffma2(acc[i][3], av[i], b1.y);
            }
        }

#pragma unroll
        for (int i = 0; i < 8; i++) {
            float s[8];
            upk2(acc[i][0], s[0], s[1]);
            upk2(acc[i][1], s[2], s[3]);
            upk2(acc[i][2], s[4], s[5]);
            upk2(acc[i][3], s[6], s[7]);
#pragma unroll
            for (int j = 0; j < 8; j++) {
                s[j] = score_xform(s[j]);
                cs[j] += s[j];
            }
            size_t base = (size_t)(qb + tm * 8 + i) * S + kb + tn * 8;
            __stcs((float4*)(Ag + base),     make_float4(s[0], s[1], s[2], s[3]));
            __stcs((float4*)(Ag + base + 4), make_float4(s[4], s[5], s[6], s[7]));
        }
    }

    __syncthreads();
    float* red = Qs;
#pragma unroll
    for (int j = 0; j < 8; j++) red[tm * 128 + tn * 8 + j] = cs[j];
    __syncthreads();
    if (tid < 128) {
        float t = 0.f;
#pragma unroll
        for (int i = 0; i < 16; i++) t += red[i * 128 + tid];
        g_NC[bh * S + kb + tid] = t;
    }
}

// ============================================================================
// Kernel 2: rc = rsqrt(N_C)  (tiny)
// ============================================================================
__global__ void k_prep() {
    int i = blockIdx.x * 256 + threadIdx.x;
    if (i < BH * S) g_RC[i] = rsqrtf(g_NC[i]);
}

// ============================================================================
// Kernel 3: rowsums. rinv[q] = 1 / sum_k s[q,k]*rc[k].
// grid (S/64, BH), 256 threads (8 warps x 8 rows each), streaming loads.
// ============================================================================
__global__ __launch_bounds__(256)
void k_rowsum(const float* __restrict__ attn) {
    const int bh = blockIdx.y;
    const int q0 = blockIdx.x * 64;
    const int w  = threadIdx.x >> 5;
    const int l  = threadIdx.x & 31;

    const float4* rc4 = (const float4*)(g_RC + bh * S);
    const float*  Ag  = attn + (size_t)bh * S * S;

    float acc[8];
#pragma unroll
    for (int r = 0; r < 8; r++) acc[r] = 0.f;

    const float4* row[8];
#pragma unroll
    for (int r = 0; r < 8; r++)
        row[r] = (const float4*)(Ag + (size_t)(q0 + w * 8 + r) * S);

#pragma unroll 2
    for (int step = 0; step < 16; step++) {
        int c = step * 32 + l;
        float4 rcv = __ldg(&rc4[c]);
#pragma unroll
        for (int r = 0; r < 8; r++) {
            float4 sv = __ldcs(&row[r][c]);
            acc[r] += sv.x * rcv.x + sv.y * rcv.y + sv.z * rcv.z + sv.w * rcv.w;
        }
    }
#pragma unroll
    for (int r = 0; r < 8; r++) {
#pragma unroll
        for (int off = 16; off; off >>= 1)
            acc[r] += __shfl_xor_sync(0xffffffffu, acc[r], off);
    }
    if (l == 0) {
#pragma unroll
        for (int r = 0; r < 8; r++)
            g_RS[bh * S + q0 + w * 8 + r] = 1.0f / acc[r];
    }
}

// ============================================================================
// Kernel 4: weights + AV GEMM. Per q-strip of 128 rows, stream k-chunks of 128:
//   w = s*rc[k]*rinv[q]; write w in-place; O += w @ V.
// smem: Ws[128][132] (k-major) | Vs[128][68]
// ============================================================================
#define K4_KC      128
#define K4_WSTRIDE 132
#define K4_VSTRIDE 68
#define K4_SMEM ((K4_KC * K4_WSTRIDE + K4_KC * K4_VSTRIDE) * 4)

__global__ __launch_bounds__(256, 2)
void k_wav(const float* __restrict__ Vg_, float* __restrict__ attn,
           float* __restrict__ Og_) {
    extern __shared__ float sm[];
    float* Ws = sm;                        // K4_KC * 132
    float* Vs = sm + K4_KC * K4_WSTRIDE;   // K4_KC * 68

    const int bh  = blockIdx.y;
    const int qb  = blockIdx.x * 128;
    const int tid = threadIdx.x;

    float*       Ag = attn + (size_t)bh * S * S;
    const float* Vg = Vg_ + (size_t)bh * S * D;
    float*       Og = Og_ + (size_t)bh * S * D;
    const float* rcg   = g_RC + bh * S;
    const float* rinvg = g_RS + bh * S;

    const int tq = tid >> 4;  // q rows tq*8..+7
    const int td = tid & 15;  // d cols td*4..+3
    unsigned long long acc[4][4];
#pragma unroll
    for (int p = 0; p < 4; p++)
#pragma unroll
        for (int j = 0; j < 4; j++) acc[p][j] = 0ull;

    for (int cb = 0; cb < S; cb += K4_KC) {
        __syncthreads();
        // stage W: rescale to final weights, write back, store transposed
        for (int t = tid; t < 128 * (K4_KC / 4); t += 256) {
            int m = t >> 5, c4 = t & 31;
            float* gp = Ag + (size_t)(qb + m) * S + cb + c4 * 4;
            float4 sv = __ldcs((const float4*)gp);
            float  ri = __ldg(rinvg + qb + m);
            float4 rcv = *(const float4*)(rcg + cb + c4 * 4);
            float4 wv;
            wv.x = sv.x * rcv.x * ri;
            wv.y = sv.y * rcv.y * ri;
            wv.z = sv.z * rcv.z * ri;
            wv.w = sv.w * rcv.w * ri;
            __stcs((float4*)gp, wv);
            int kx = c4 * 4;
            Ws[(kx + 0) * K4_WSTRIDE + m] = wv.x;
            Ws[(kx + 1) * K4_WSTRIDE + m] = wv.y;
            Ws[(kx + 2) * K4_WSTRIDE + m] = wv.z;
            Ws[(kx + 3) * K4_WSTRIDE + m] = wv.w;
        }
        // stage V
        for (int t = tid; t < K4_KC * 16; t += 256) {
            int k = t >> 4, c4 = t & 15;
            *(float4*)(Vs + k * K4_VSTRIDE + c4 * 4) =
                *(const float4*)(Vg + (size_t)(cb + k) * D + c4 * 4);
        }
        __syncthreads();

#pragma unroll 8
        for (int kk = 0; kk < K4_KC; kk++) {
            ulonglong2 a01 = *(const ulonglong2*)(Ws + kk * K4_WSTRIDE + tq * 8);
            ulonglong2 a23 = *(const ulonglong2*)(Ws + kk * K4_WSTRIDE + tq * 8 + 4);
            float4 bv = *(const float4*)(Vs + kk * K4_VSTRIDE + td * 4);
            unsigned long long bd[4] = {pk2(bv.x, bv.x), pk2(bv.y, bv.y),
                                        pk2(bv.z, bv.z), pk2(bv.w, bv.w)};
            unsigned long long aa[4] = {a01.x, a01.y, a23.x, a23.y};
#pragma unroll
            for (int p = 0; p < 4; p++) {
                ffma2(acc[p][0], aa[p], bd[0]);
                ffma2(acc[p][1], aa[p], bd[1]);
                ffma2(acc[p][2], aa[p], bd[2]);
                ffma2(acc[p][3], aa[p], bd[3]);
            }
        }
    }

#pragma unroll
    for (int p = 0; p < 4; p++) {
        float x0, y0, x1, y1, x2, y2, x3, y3;
        upk2(acc[p][0], x0, y0);
        upk2(acc[p][1], x1, y1);
        upk2(acc[p][2], x2, y2);
        upk2(acc[p][3], x3, y3);
        int q0 = qb + tq * 8 + 2 * p;
        *(float4*)(Og + (size_t)q0 * D + td * 4)       = make_float4(x0, x1, x2, x3);
        *(float4*)(Og + (size_t)(q0 + 1) * D + td * 4) = make_float4(y0, y1, y2, y3);
    }
}

// ============================================================================
extern "C" void kernel_launch(void* const* d_in, const int* in_sizes, int n_in,
                              void* d_out, int out_size) {
    const float* q = (const float*)d_in[0];
    const float* k = (const float*)d_in[1];
    const float* v = (const float*)d_in[2];
    // d_in[3] = attn_mask (all False) — no-op in reference.

    float* out  = (float*)d_out;
    float* O    = out;                       // [B,H,S,D]
    float* attn = out + (size_t)BH * S * D;  // [B,H,S,S]

    cudaFuncSetAttribute(k_scores, cudaFuncAttributeMaxDynamicSharedMemorySize, K1_SMEM);
    cudaFuncSetAttribute(k_wav,    cudaFuncAttributeMaxDynamicSharedMemorySize, K4_SMEM);

    dim3 g1(S / 128, BH);
    k_scores<<<g1, 256, K1_SMEM>>>(q, k, attn);

    k_prep<<<(BH * S + 255) / 256, 256>>>();

    dim3 g3(S / 64, BH);
    k_rowsum<<<g3, 256>>>(attn);

    dim3 g4(S / 128, BH);
    k_wav<<<g4, 256, K4_SMEM>>>(v, attn, O);
}